// round 2
// baseline (speedup 1.0000x reference)
#include <cuda_runtime.h>
#include <cuda_bf16.h>

// Problem constants
#define B_    8
#define H_    256
#define P_    225          // H - KER + 1
#define KER_  32
#define HALF_ 16
#define K_    2
#define CDA_  64
#define NBC_  16           // B * 2 classes

// Output section offsets (floats), reference tuple flattened in order:
// classifer_p [2,2,8,2,32,32], feat_p [2,2,8,64,32,32], vals [2,2,8],
// pesudo_p [2,2,8,1,32,32], true_p [2,2,8,1,32,32], oxy [2,2,8,2,2]
#define OFF_CLS   0
#define OFF_FEAT  65536
#define OFF_VALS  2162688
#define OFF_PES   2162720
#define OFF_TRUE  2195488
#define OFF_OXY   2228256

// Scratch (no allocations allowed)
__device__ float g_rowsum[NBC_ * H_ * P_];   // per (b,c): [256 rows][225 window sums]
__device__ float g_pooled[NBC_ * P_ * P_];   // per (b,c): [225][225]
__device__ int   g_selpx[NBC_ * K_];
__device__ int   g_selpy[NBC_ * K_];

// ---------------------------------------------------------------------------
// Kernel 1: softmax over C=2 + horizontal 32-window sums.
// grid = B*H blocks (one per (b, row)), 256 threads.
// ---------------------------------------------------------------------------
__global__ void k_rowsum(const float* __restrict__ infeat) {
    int by = blockIdx.x;
    int b = by >> 8;
    int y = by & 255;
    int x = threadIdx.x;

    __shared__ float p0[H_];
    __shared__ float p1[H_];

    float x0 = infeat[((b * 2 + 0) * H_ + y) * H_ + x];
    float x1 = infeat[((b * 2 + 1) * H_ + y) * H_ + x];
    float m  = fmaxf(x0, x1);
    float e0 = expf(x0 - m);
    float e1 = expf(x1 - m);
    float inv = 1.0f / (e0 + e1);
    p0[x] = e0 * inv;
    p1[x] = e1 * inv;
    __syncthreads();

    if (x < P_) {
        float s0 = 0.0f, s1 = 0.0f;
#pragma unroll
        for (int i = 0; i < KER_; i++) {
            s0 += p0[x + i];
            s1 += p1[x + i];
        }
        g_rowsum[((b * 2 + 0) * H_ + y) * P_ + x] = s0;
        g_rowsum[((b * 2 + 1) * H_ + y) * P_ + x] = s1;
    }
}

// ---------------------------------------------------------------------------
// Kernel 2: vertical sliding 32-window over rowsums -> pooled map / 1024.
// grid = (16 bc, 15 py-chunks), 256 threads (225 active, one per px).
// ---------------------------------------------------------------------------
__global__ void k_pool() {
    int bc = blockIdx.x;
    int chunk = blockIdx.y;        // 15 chunks of 15 rows
    int px = threadIdx.x;
    if (px >= P_) return;

    int py0 = chunk * 15;
    const float* rs = g_rowsum + bc * H_ * P_;
    float* out = g_pooled + bc * P_ * P_;

    float s = 0.0f;
#pragma unroll
    for (int i = 0; i < KER_; i++) s += rs[(py0 + i) * P_ + px];
    out[py0 * P_ + px] = s * (1.0f / 1024.0f);

    for (int py = py0 + 1; py < py0 + 15; py++) {
        s += rs[(py + 31) * P_ + px] - rs[(py - 1) * P_ + px];
        out[py * P_ + px] = s * (1.0f / 1024.0f);
    }
}

// ---------------------------------------------------------------------------
// Kernel 3: greedy top-2 with window suppression; writes vals + oxy to d_out.
// grid = 16 blocks (one per (b, class)), 256 threads.
// Tie-break: lowest flat index (JAX argmax). Suppression sets v = 0
// (equivalent to reference's mask-multiply, pooled values are positive).
// ---------------------------------------------------------------------------
__global__ void k_select(float* __restrict__ out) {
    int bc = blockIdx.x;           // b*2 + c
    int b = bc >> 1;
    int c = bc & 1;
    const float* pm = g_pooled + bc * P_ * P_;
    const int N = P_ * P_;

    __shared__ float sv[256];
    __shared__ int   si[256];

    int sel_px[K_], sel_py[K_];
    float sel_val[K_];

    for (int j = 0; j < K_; j++) {
        float best = -1e30f;
        int bi = 0x7fffffff;
        for (int i = threadIdx.x; i < N; i += 256) {
            float v = pm[i];
            if (j == 1) {
                int py = i / P_;
                int px = i - py * P_;
                bool sup = (py >= sel_py[0] - HALF_) && (py < sel_py[0] + HALF_) &&
                           (px >= sel_px[0] - HALF_) && (px < sel_px[0] + HALF_);
                if (sup) v = 0.0f;
            }
            if (v > best || (v == best && i < bi)) { best = v; bi = i; }
        }
        sv[threadIdx.x] = best;
        si[threadIdx.x] = bi;
        __syncthreads();
        for (int s = 128; s > 0; s >>= 1) {
            if (threadIdx.x < s) {
                float ov = sv[threadIdx.x + s];
                int   oi = si[threadIdx.x + s];
                if (ov > sv[threadIdx.x] ||
                    (ov == sv[threadIdx.x] && oi < si[threadIdx.x])) {
                    sv[threadIdx.x] = ov;
                    si[threadIdx.x] = oi;
                }
            }
            __syncthreads();
        }
        int idx = si[0];
        float val = sv[0];
        sel_py[j] = idx / P_;
        sel_px[j] = idx - sel_py[j] * P_;
        sel_val[j] = val;
        __syncthreads();   // all threads done reading sv[0]/si[0] before next pass
    }

    if (threadIdx.x < K_) {
        int j = threadIdx.x;
        g_selpx[bc * K_ + j] = sel_px[j];
        g_selpy[bc * K_ + j] = sel_py[j];
        // vals[c][j][b]
        out[OFF_VALS + (c * K_ + j) * B_ + b] = sel_val[j];
        // oxy[c][j][b][{x,y}][{lo,hi}]
        int o = OFF_OXY + ((c * K_ + j) * B_ + b) * 4;
        out[o + 0] = (float)sel_px[j];
        out[o + 1] = (float)(sel_px[j] + KER_ - 1);
        out[o + 2] = (float)sel_py[j];
        out[o + 3] = (float)(sel_py[j] + KER_ - 1);
    }
}

// ---------------------------------------------------------------------------
// Kernel 4: patch extraction gather.
// Block linear index covers sections:
//   [0,64)        classifer (c,j,b,ch2)  from infeat
//   [64,2112)     feat      (c,j,b,ch64) from FeatureDA
//   [2112,2144)   pesudo    (c,j,b)      from labelTpesudo
//   [2144,2176)   true      (c,j,b)      from labelT
// Each block copies one 32x32 patch (1024 floats) with 256 threads.
// ---------------------------------------------------------------------------
__global__ void k_extract(const float* __restrict__ infeat,
                          const float* __restrict__ pesudo,
                          const float* __restrict__ labelT,
                          const float* __restrict__ feat,
                          float* __restrict__ out) {
    int blk = blockIdx.x;
    const float* src;
    int Csrc, ch, c, j, b;
    long base;

    if (blk < 64) {
        int t = blk;
        ch = t & 1;  t >>= 1;
        b  = t & 7;  t >>= 3;
        j  = t & 1;  t >>= 1;
        c  = t;
        src = infeat; Csrc = 2;
        base = OFF_CLS + (long)blk * 1024;
    } else if (blk < 2112) {
        int t = blk - 64;
        int local = t;
        ch = t & 63; t >>= 6;
        b  = t & 7;  t >>= 3;
        j  = t & 1;  t >>= 1;
        c  = t;
        src = feat; Csrc = CDA_;
        base = OFF_FEAT + (long)local * 1024;
    } else if (blk < 2144) {
        int t = blk - 2112;
        int local = t;
        ch = 0;
        b  = t & 7;  t >>= 3;
        j  = t & 1;  t >>= 1;
        c  = t;
        src = pesudo; Csrc = 1;
        base = OFF_PES + (long)local * 1024;
    } else {
        int t = blk - 2144;
        int local = t;
        ch = 0;
        b  = t & 7;  t >>= 3;
        j  = t & 1;  t >>= 1;
        c  = t;
        src = labelT; Csrc = 1;
        base = OFF_TRUE + (long)local * 1024;
    }

    int sel = (b * 2 + c) * K_ + j;
    int px = g_selpx[sel];
    int py = g_selpy[sel];

    const float* s = src + (((long)b * Csrc + ch) * H_ + py) * H_ + px;
#pragma unroll
    for (int e = threadIdx.x; e < 1024; e += 256) {
        int dy = e >> 5;
        int dx = e & 31;
        out[base + e] = s[dy * H_ + dx];
    }
}

// ---------------------------------------------------------------------------
extern "C" void kernel_launch(void* const* d_in, const int* in_sizes, int n_in,
                              void* d_out, int out_size) {
    const float* infeat  = (const float*)d_in[0];
    const float* pesudo  = (const float*)d_in[1];
    const float* labelT  = (const float*)d_in[2];
    const float* featDA  = (const float*)d_in[3];
    // d_in[4] is k (=2), baked in as K_.
    float* out = (float*)d_out;

    k_rowsum<<<B_ * H_, 256>>>(infeat);
    dim3 g2(NBC_, 15);
    k_pool<<<g2, 256>>>();
    k_select<<<NBC_, 256>>>(out);
    k_extract<<<2176, 256>>>(infeat, pesudo, labelT, featDA, out);
}

// round 3
// speedup vs baseline: 1.3614x; 1.3614x over previous
#include <cuda_runtime.h>
#include <cuda_bf16.h>

// Problem constants
#define B_    8
#define H_    256
#define P_    225          // H - KER + 1
#define KER_  32
#define HALF_ 16
#define K_    2
#define CDA_  64
#define NBC_  16           // B * 2 classes
#define NRB_  15           // row-blocks per map (15 rows each)

// Output section offsets (floats)
#define OFF_CLS   0
#define OFF_FEAT  65536
#define OFF_VALS  2162688
#define OFF_PES   2162720
#define OFF_TRUE  2195488
#define OFF_OXY   2228256

// Scratch
__device__ float g_rowsum[NBC_ * H_ * P_];
__device__ float g_pooled[NBC_ * P_ * P_];
__device__ float g_pval[NBC_ * NRB_];
__device__ int   g_pidx[NBC_ * NRB_];
__device__ int   g_selpx[NBC_ * K_];
__device__ int   g_selpy[NBC_ * K_];

// ---------------------------------------------------------------------------
// Kernel 1: softmax over C=2 + horizontal 32-window sums.
// ---------------------------------------------------------------------------
__global__ void k_rowsum(const float* __restrict__ infeat) {
    int by = blockIdx.x;
    int b = by >> 8;
    int y = by & 255;
    int x = threadIdx.x;

    __shared__ float p0[H_];
    __shared__ float p1[H_];

    float x0 = infeat[((b * 2 + 0) * H_ + y) * H_ + x];
    float x1 = infeat[((b * 2 + 1) * H_ + y) * H_ + x];
    float m  = fmaxf(x0, x1);
    float e0 = expf(x0 - m);
    float e1 = expf(x1 - m);
    float inv = 1.0f / (e0 + e1);
    p0[x] = e0 * inv;
    p1[x] = e1 * inv;
    __syncthreads();

    if (x < P_) {
        float s0 = 0.0f, s1 = 0.0f;
#pragma unroll
        for (int i = 0; i < KER_; i++) {
            s0 += p0[x + i];
            s1 += p1[x + i];
        }
        g_rowsum[((b * 2 + 0) * H_ + y) * P_ + x] = s0;
        g_rowsum[((b * 2 + 1) * H_ + y) * P_ + x] = s1;
    }
}

// ---------------------------------------------------------------------------
// Kernel 2: vertical 32-window pooling (15 rows per block) FUSED with
// per-block argmax partial (value + lowest flat index).
// grid = (16 bc, 15 row-blocks), 256 threads (225 active).
// ---------------------------------------------------------------------------
__global__ void k_poolpart() {
    int bc = blockIdx.x;
    int chunk = blockIdx.y;
    int px = threadIdx.x;

    const float* rs = g_rowsum + bc * H_ * P_;
    float* outp = g_pooled + bc * P_ * P_;

    float best = -1e30f;
    int bi = 0x7fffffff;

    if (px < P_) {
        int py0 = chunk * 15;
        float s = 0.0f;
#pragma unroll
        for (int i = 0; i < KER_; i++) s += rs[(py0 + i) * P_ + px];
        float v = s * (1.0f / 1024.0f);
        outp[py0 * P_ + px] = v;
        best = v; bi = py0 * P_ + px;
        for (int py = py0 + 1; py < py0 + 15; py++) {
            s += rs[(py + 31) * P_ + px] - rs[(py - 1) * P_ + px];
            v = s * (1.0f / 1024.0f);
            outp[py * P_ + px] = v;
            if (v > best) { best = v; bi = py * P_ + px; } // strict >: lowest idx kept
        }
    }

    __shared__ float sv[256];
    __shared__ int   si[256];
    sv[threadIdx.x] = best;
    si[threadIdx.x] = bi;
    __syncthreads();
    for (int s = 128; s > 0; s >>= 1) {
        if (threadIdx.x < s) {
            float ov = sv[threadIdx.x + s];
            int   oi = si[threadIdx.x + s];
            if (ov > sv[threadIdx.x] ||
                (ov == sv[threadIdx.x] && oi < si[threadIdx.x])) {
                sv[threadIdx.x] = ov; si[threadIdx.x] = oi;
            }
        }
        __syncthreads();
    }
    if (threadIdx.x == 0) {
        g_pval[bc * NRB_ + chunk] = sv[0];
        g_pidx[bc * NRB_ + chunk] = si[0];
    }
}

// ---------------------------------------------------------------------------
// Kernel 3: final selection. Pass 1 = reduce 15 partials. Pass 2 = rescan only
// the row-blocks touched by the suppression window (<=4 of 15), combine with
// untouched partials. Writes vals + oxy to d_out, selections to globals.
// grid = 16 blocks, 256 threads.
// ---------------------------------------------------------------------------
__global__ void k_select2(float* __restrict__ out) {
    int bc = blockIdx.x;
    int b = bc >> 1;
    int c = bc & 1;
    const float* pm = g_pooled + bc * P_ * P_;

    __shared__ float sv[256];
    __shared__ int   si[256];

    // ---- pass 1: reduce partials ----
    float best = -1e30f;
    int bi = 0x7fffffff;
    if (threadIdx.x < NRB_) {
        best = g_pval[bc * NRB_ + threadIdx.x];
        bi   = g_pidx[bc * NRB_ + threadIdx.x];
    }
    sv[threadIdx.x] = best; si[threadIdx.x] = bi;
    __syncthreads();
    for (int s = 128; s > 0; s >>= 1) {
        if (threadIdx.x < s) {
            float ov = sv[threadIdx.x + s];
            int   oi = si[threadIdx.x + s];
            if (ov > sv[threadIdx.x] ||
                (ov == sv[threadIdx.x] && oi < si[threadIdx.x])) {
                sv[threadIdx.x] = ov; si[threadIdx.x] = oi;
            }
        }
        __syncthreads();
    }
    int idx0 = si[0];
    float val0 = sv[0];
    int py0 = idx0 / P_;
    int px0 = idx0 - py0 * P_;
    __syncthreads();

    // ---- pass 2: rescan affected row-blocks with suppression ----
    int lo  = max(0, py0 - HALF_), hi  = min(P_, py0 + HALF_);
    int clo = max(0, px0 - HALF_), chi = min(P_, px0 + HALF_);
    int rblo = lo / 15, rbhi = (hi - 1) / 15;
    int rlo = rblo * 15;
    int rhi = min(P_, (rbhi + 1) * 15);

    best = -1e30f; bi = 0x7fffffff;
    if (threadIdx.x < NRB_ && ((int)threadIdx.x < rblo || (int)threadIdx.x > rbhi)) {
        best = g_pval[bc * NRB_ + threadIdx.x];
        bi   = g_pidx[bc * NRB_ + threadIdx.x];
    }
    int n = (rhi - rlo) * P_;
    for (int i = threadIdx.x; i < n; i += 256) {
        int r  = i / P_;
        int cc = i - r * P_;
        r += rlo;
        int idx = r * P_ + cc;
        float v = pm[idx];
        if (r >= lo && r < hi && cc >= clo && cc < chi) v = 0.0f;
        if (v > best || (v == best && idx < bi)) { best = v; bi = idx; }
    }
    sv[threadIdx.x] = best; si[threadIdx.x] = bi;
    __syncthreads();
    for (int s = 128; s > 0; s >>= 1) {
        if (threadIdx.x < s) {
            float ov = sv[threadIdx.x + s];
            int   oi = si[threadIdx.x + s];
            if (ov > sv[threadIdx.x] ||
                (ov == sv[threadIdx.x] && oi < si[threadIdx.x])) {
                sv[threadIdx.x] = ov; si[threadIdx.x] = oi;
            }
        }
        __syncthreads();
    }

    if (threadIdx.x == 0) {
        int idx1 = si[0];
        float val1 = sv[0];
        int py1 = idx1 / P_;
        int px1 = idx1 - py1 * P_;

        int pxs[K_] = {px0, px1};
        int pys[K_] = {py0, py1};
        float vals[K_] = {val0, val1};
#pragma unroll
        for (int j = 0; j < K_; j++) {
            g_selpx[bc * K_ + j] = pxs[j];
            g_selpy[bc * K_ + j] = pys[j];
            out[OFF_VALS + (c * K_ + j) * B_ + b] = vals[j];
            int o = OFF_OXY + ((c * K_ + j) * B_ + b) * 4;
            out[o + 0] = (float)pxs[j];
            out[o + 1] = (float)(pxs[j] + KER_ - 1);
            out[o + 2] = (float)pys[j];
            out[o + 3] = (float)(pys[j] + KER_ - 1);
        }
    }
}

// ---------------------------------------------------------------------------
// Kernel 4: patch gather, vectorized: thread = 4 consecutive floats,
// STG.128 store, 4 independent scalar loads.
// ---------------------------------------------------------------------------
__global__ void k_extract(const float* __restrict__ infeat,
                          const float* __restrict__ pesudo,
                          const float* __restrict__ labelT,
                          const float* __restrict__ feat,
                          float* __restrict__ out) {
    int blk = blockIdx.x;
    const float* src;
    int Csrc, ch, c, j, b;
    long base;

    if (blk < 64) {
        int t = blk;
        ch = t & 1;  t >>= 1;
        b  = t & 7;  t >>= 3;
        j  = t & 1;  t >>= 1;
        c  = t;
        src = infeat; Csrc = 2;
        base = OFF_CLS + (long)blk * 1024;
    } else if (blk < 2112) {
        int t = blk - 64;
        int local = t;
        ch = t & 63; t >>= 6;
        b  = t & 7;  t >>= 3;
        j  = t & 1;  t >>= 1;
        c  = t;
        src = feat; Csrc = CDA_;
        base = OFF_FEAT + (long)local * 1024;
    } else if (blk < 2144) {
        int t = blk - 2112;
        int local = t;
        ch = 0;
        b  = t & 7;  t >>= 3;
        j  = t & 1;  t >>= 1;
        c  = t;
        src = pesudo; Csrc = 1;
        base = OFF_PES + (long)local * 1024;
    } else {
        int t = blk - 2144;
        int local = t;
        ch = 0;
        b  = t & 7;  t >>= 3;
        j  = t & 1;  t >>= 1;
        c  = t;
        src = labelT; Csrc = 1;
        base = OFF_TRUE + (long)local * 1024;
    }

    int sel = (b * 2 + c) * K_ + j;
    int px = g_selpx[sel];
    int py = g_selpy[sel];

    const float* s = src + (((long)b * Csrc + ch) * H_ + py) * H_ + px;

    int t = threadIdx.x;          // 256 threads, 4 floats each
    int dy = t >> 3;              // (4t)/32
    int dx = (t & 7) * 4;
    const float* sp = s + dy * H_ + dx;
    float4 v;
    v.x = sp[0]; v.y = sp[1]; v.z = sp[2]; v.w = sp[3];
    *reinterpret_cast<float4*>(out + base + (long)t * 4) = v;
}

// ---------------------------------------------------------------------------
extern "C" void kernel_launch(void* const* d_in, const int* in_sizes, int n_in,
                              void* d_out, int out_size) {
    const float* infeat  = (const float*)d_in[0];
    const float* pesudo  = (const float*)d_in[1];
    const float* labelT  = (const float*)d_in[2];
    const float* featDA  = (const float*)d_in[3];
    float* out = (float*)d_out;

    k_rowsum<<<B_ * H_, 256>>>(infeat);
    dim3 g2(NBC_, NRB_);
    k_poolpart<<<g2, 256>>>();
    k_select2<<<NBC_, 256>>>(out);
    k_extract<<<2176, 256>>>(infeat, pesudo, labelT, featDA, out);
}